// round 9
// baseline (speedup 1.0000x reference)
#include <cuda_runtime.h>
#include <cuda_bf16.h>

#define E_MAX   250000
#define DIM     64

// Scratch (alloc-free rule: __device__ globals; zero-initialized at load).
// g_segsum / g_rowsum are re-zeroed at the END of each call (k_norm) so every
// call — including the first — starts from zeros.
__device__ float g_ev[E_MAX];      // exp(logit) per edge
__device__ float g_segsum[E_MAX];  // sum of exp per idx_vi segment
__device__ float g_rowsum[64];     // per-batch row sums (B<=64)

// ---------------------------------------------------------------------------
// K1: out-zero prologue + logits + exp + segment-sum.
//   One 16-lane group per PAIR of consecutive edges: 10 independent float4
//   gathers issued up-front per thread (2x MLP vs one-edge groups). When the
//   pair shares idx_vi (contiguous segment), the vi-side rows are loaded once
//   and the two segsum atomics merge into one.
//   No max-subtraction: logits are O(1), exp(x)/sum exp(x) == softmax.
// ---------------------------------------------------------------------------
__global__ void __launch_bounds__(256)
k_logits(const int*   __restrict__ edges,
         const float* __restrict__ hc,
         const float* __restrict__ hu,
         const float* __restrict__ rel_emb,
         const float* __restrict__ ws,
         const float* __restrict__ bvec,
         const float* __restrict__ out_w,
         const float* __restrict__ out_b,
         float4*      __restrict__ out4,
         int n4, int E)
{
    __shared__ float s_ws[8 * DIM];
    __shared__ float s_b[DIM], s_ow[DIM], s_ob[DIM];
    int tid = threadIdx.x;
    int gt  = blockIdx.x * blockDim.x + tid;

    // zero the output (K1 never touches out otherwise -> race-free)
    if (gt < n4) out4[gt] = make_float4(0.f, 0.f, 0.f, 0.f);

    for (int i = tid; i < 8 * DIM; i += blockDim.x) s_ws[i] = ws[i];
    for (int i = tid; i < DIM; i += blockDim.x) {
        s_b[i]  = bvec[i];
        s_ow[i] = out_w[i];
        s_ob[i] = out_b[i];
    }
    __syncthreads();

    int grp  = gt >> 4;          // group index: handles edges 2*grp, 2*grp+1
    int lane = tid & 15;
    unsigned gmask = 0xFFFFu << (tid & 16);

    int e0 = grp * 2;
    if (e0 >= E) return;
    bool has1 = (e0 + 1 < E);

    const int* r0 = edges + (size_t)e0 * 8;
    const int* r1 = r0 + 8;
    int vi0   = __ldg(r0 + 1), vj0 = __ldg(r0 + 2), rl0 = __ldg(r0 + 3);
    int ivi0  = __ldg(r0 + 4);
    int e2vi0 = __ldg(r0 + 6), e2vj0 = __ldg(r0 + 7);
    int vi1 = vi0, vj1 = vj0, rl1 = rl0, ivi1 = ivi0, e2vi1 = e2vi0, e2vj1 = e2vj0;
    if (has1) {
        vi1   = __ldg(r1 + 1); vj1 = __ldg(r1 + 2); rl1 = __ldg(r1 + 3);
        ivi1  = __ldg(r1 + 4);
        e2vi1 = __ldg(r1 + 6); e2vj1 = __ldg(r1 + 7);
    }
    bool share = (ivi1 == ivi0);   // group-uniform

    int d0 = lane * 4;
    // edge 0 gathers
    float4 a0  = *reinterpret_cast<const float4*>(hc + (size_t)e2vi0 * DIM + d0);
    float4 c0  = *reinterpret_cast<const float4*>(hc + (size_t)e2vj0 * DIM + d0);
    float4 A0  = *reinterpret_cast<const float4*>(hu + (size_t)vi0   * DIM + d0);
    float4 C0  = *reinterpret_cast<const float4*>(hu + (size_t)vj0   * DIM + d0);
    float4 rr0 = *reinterpret_cast<const float4*>(rel_emb + (size_t)rl0 * DIM + d0);
    // edge 1 gathers (vi-side reused when segment shared)
    float4 a1 = a0, A1 = A0;
    if (!share) {
        a1 = *reinterpret_cast<const float4*>(hc + (size_t)e2vi1 * DIM + d0);
        A1 = *reinterpret_cast<const float4*>(hu + (size_t)vi1   * DIM + d0);
    }
    float4 c1  = *reinterpret_cast<const float4*>(hc + (size_t)e2vj1 * DIM + d0);
    float4 C1  = *reinterpret_cast<const float4*>(hu + (size_t)vj1   * DIM + d0);
    float4 rr1 = *reinterpret_cast<const float4*>(rel_emb + (size_t)rl1 * DIM + d0);

    float av0[4] = {a0.x, a0.y, a0.z, a0.w}, cv0[4] = {c0.x, c0.y, c0.z, c0.w};
    float Av0[4] = {A0.x, A0.y, A0.z, A0.w}, Cv0[4] = {C0.x, C0.y, C0.z, C0.w};
    float rv0[4] = {rr0.x, rr0.y, rr0.z, rr0.w};
    float av1[4] = {a1.x, a1.y, a1.z, a1.w}, cv1[4] = {c1.x, c1.y, c1.z, c1.w};
    float Av1[4] = {A1.x, A1.y, A1.z, A1.w}, Cv1[4] = {C1.x, C1.y, C1.z, C1.w};
    float rv1[4] = {rr1.x, rr1.y, rr1.z, rr1.w};

    float acc0 = 0.0f, acc1 = 0.0f;
#pragma unroll
    for (int j = 0; j < 4; j++) {
        int d = d0 + j;
        float w01 = s_ws[0 * DIM + d], w1 = s_ws[1 * DIM + d];
        float w2  = s_ws[2 * DIM + d], w3 = s_ws[3 * DIM + d];
        float w4  = s_ws[4 * DIM + d], w5 = s_ws[5 * DIM + d];
        float w6  = s_ws[6 * DIM + d], w7 = s_ws[7 * DIM + d];
        float bb = s_b[d], ow = s_ow[d], ob = s_ob[d];

        float f0 = bb
                 + av0[j] * cv0[j] * fmaf(w1, rv0[j], w01)
                 + av0[j] * Cv0[j] * fmaf(w3, rv0[j], w2)
                 + Av0[j] * cv0[j] * fmaf(w5, rv0[j], w4)
                 + Av0[j] * Cv0[j] * fmaf(w7, rv0[j], w6);
        acc0 += fmaxf(f0, 0.0f) * ow + ob;

        float f1 = bb
                 + av1[j] * cv1[j] * fmaf(w1, rv1[j], w01)
                 + av1[j] * Cv1[j] * fmaf(w3, rv1[j], w2)
                 + Av1[j] * cv1[j] * fmaf(w5, rv1[j], w4)
                 + Av1[j] * Cv1[j] * fmaf(w7, rv1[j], w6);
        acc1 += fmaxf(f1, 0.0f) * ow + ob;
    }

#pragma unroll
    for (int off = 8; off; off >>= 1) {
        acc0 += __shfl_xor_sync(gmask, acc0, off);
        acc1 += __shfl_xor_sync(gmask, acc1, off);
    }

    if (lane == 0) {
        float ev0 = __expf(acc0);
        g_ev[e0] = ev0;
        if (has1) {
            float ev1 = __expf(acc1);
            g_ev[e0 + 1] = ev1;
            if (share) {
                atomicAdd(&g_segsum[ivi0], ev0 + ev1);
            } else {
                atomicAdd(&g_segsum[ivi0], ev0);
                atomicAdd(&g_segsum[ivi1], ev1);
            }
        } else {
            atomicAdd(&g_segsum[ivi0], ev0);
        }
    }
}

// ---------------------------------------------------------------------------
// K2: thread-per-edge scatter + warp-aggregated rowsum.
// ---------------------------------------------------------------------------
__global__ void __launch_bounds__(256)
k_scatter(const int*   __restrict__ edges,
          const float* __restrict__ na,
          const float* __restrict__ ey,
          float*       __restrict__ out,
          int N, int E)
{
    int e  = blockIdx.x * blockDim.x + threadIdx.x;
    int ec = min(e, E - 1);
    const int* row = edges + (size_t)ec * 8;
    int idx = __ldg(row + 0);

    float ta = 0.0f;
    if (e < E) {
        int vi  = __ldg(row + 1);
        int vj  = __ldg(row + 2);
        int ivi = __ldg(row + 4);
        float tr = g_ev[e] * __fdividef(1.0f, g_segsum[ivi]);
        ta = __ldg(na + (size_t)idx * N + vi) * tr * __ldg(ey + e);
        atomicAdd(&out[(size_t)idx * N + vj], ta);
    }

    int idx0 = __shfl_sync(0xffffffffu, idx, 0);
    bool uni = __all_sync(0xffffffffu, idx == idx0);
    if (uni) {
        float w = ta;
#pragma unroll
        for (int off = 16; off; off >>= 1)
            w += __shfl_xor_sync(0xffffffffu, w, off);
        if ((threadIdx.x & 31) == 0 && w != 0.0f)
            atomicAdd(&g_rowsum[idx0], w);
    } else if (ta != 0.0f) {
        atomicAdd(&g_rowsum[idx], ta);
    }
}

// ---------------------------------------------------------------------------
// K3: normalize rows (float4, reciprocal) + re-zero scratch for next call.
// ---------------------------------------------------------------------------
__global__ void k_norm(float4* __restrict__ out4, int N, int n4, int E) {
    int i = blockIdx.x * blockDim.x + threadIdx.x;
    int stride = gridDim.x * blockDim.x;
    if (i < n4) {
        int row = (i * 4) / N;
        float inv = __fdividef(1.0f, g_rowsum[row]);
        float4 v = out4[i];
        v.x *= inv; v.y *= inv; v.z *= inv; v.w *= inv;
        out4[i] = v;
    }
    // re-zero scratch so the NEXT kernel_launch starts clean
    float4* ss4 = reinterpret_cast<float4*>(g_segsum);
    int e4 = (E + 3) / 4;
    float4 z = make_float4(0.f, 0.f, 0.f, 0.f);
    for (int k = i; k < e4; k += stride) ss4[k] = z;
    if (i < 64) g_rowsum[i] = 0.0f;
}

// ---------------------------------------------------------------------------
// Inputs (metadata order):
//  0 node_attention (B*N f32)   1 selected_edges (E*8 i32)  2 edges_y (E f32)
//  3 hidden_con (n_vis*64 f32)  4 hidden_uncon (N*64 f32)   5 rel_emb (R*64 f32)
//  6 ws (8*64 f32)  7 b (64)  8 out_w (64)  9 out_b (64)
// ---------------------------------------------------------------------------
extern "C" void kernel_launch(void* const* d_in, const int* in_sizes, int n_in,
                              void* d_out, int out_size)
{
    const float* na   = (const float*)d_in[0];
    const int*   sel  = (const int*)  d_in[1];
    const float* ey   = (const float*)d_in[2];
    const float* hc   = (const float*)d_in[3];
    const float* hu   = (const float*)d_in[4];
    const float* rel  = (const float*)d_in[5];
    const float* ws   = (const float*)d_in[6];
    const float* bv   = (const float*)d_in[7];
    const float* ow   = (const float*)d_in[8];
    const float* ob   = (const float*)d_in[9];
    float* out = (float*)d_out;

    int E  = in_sizes[2];
    int BN = in_sizes[0];
    int N  = in_sizes[4] / DIM;
    int n4 = BN / 4;

    // 16 lanes per edge-PAIR: ceil(E/2) groups
    int groups  = (E + 1) / 2;
    int blocks1 = (groups * 16 + 255) / 256;
    k_logits<<<blocks1, 256>>>(sel, hc, hu, rel, ws, bv, ow, ob,
                               (float4*)out, n4, E);

    int tb = 256;
    k_scatter<<<(E + tb - 1) / tb, tb>>>(sel, na, ey, out, N, E);
    k_norm<<<(n4 + 255) / 256, 256>>>((float4*)out, N, n4, E);
}

// round 10
// speedup vs baseline: 1.2240x; 1.2240x over previous
#include <cuda_runtime.h>
#include <cuda_fp16.h>

#define E_MAX    250000
#define DIM      64
#define HC_ROWS  200000   // n_visited <= B*N = 200000
#define HU_ROWS  50000
#define REL_ROWS 500

// Scratch (alloc-free rule: __device__ globals; zero-initialized at load).
// g_segsum / g_rowsum are re-zeroed at the END of each call (k_norm).
__device__ float  g_ev[E_MAX];
__device__ float  g_segsum[E_MAX];
__device__ float  g_rowsum[64];
// fp16 copies of the gather tables (halves gather bytes; precision margin ~100x)
__device__ __half g_hc_h[HC_ROWS * DIM];
__device__ __half g_hu_h[HU_ROWS * DIM];
__device__ __half g_rel_h[REL_ROWS * DIM];

__device__ __forceinline__ uint2 pack_half4(float4 v) {
    __half2 lo = __float22half2_rn(make_float2(v.x, v.y));
    __half2 hi = __float22half2_rn(make_float2(v.z, v.w));
    uint2 u;
    u.x = *reinterpret_cast<unsigned*>(&lo);
    u.y = *reinterpret_cast<unsigned*>(&hi);
    return u;
}

// ---------------------------------------------------------------------------
// K0: zero output + convert hc/hu/rel f32 -> f16
// ---------------------------------------------------------------------------
__global__ void k_prep(const float4* __restrict__ hc4,
                       const float4* __restrict__ hu4,
                       const float4* __restrict__ rel4,
                       float4*       __restrict__ out4,
                       int n4, int nhc4, int nhu4, int nrel4)
{
    int stride = gridDim.x * blockDim.x;
    int i0 = blockIdx.x * blockDim.x + threadIdx.x;
    float4 z = make_float4(0.f, 0.f, 0.f, 0.f);
    for (int i = i0; i < n4; i += stride) out4[i] = z;

    uint2* hc_h  = reinterpret_cast<uint2*>(g_hc_h);
    uint2* hu_h  = reinterpret_cast<uint2*>(g_hu_h);
    uint2* rel_h = reinterpret_cast<uint2*>(g_rel_h);
    for (int i = i0; i < nhc4;  i += stride) hc_h[i]  = pack_half4(__ldg(hc4 + i));
    for (int i = i0; i < nhu4;  i += stride) hu_h[i]  = pack_half4(__ldg(hu4 + i));
    for (int i = i0; i < nrel4; i += stride) rel_h[i] = pack_half4(__ldg(rel4 + i));
}

// ---------------------------------------------------------------------------
// K1: logits from fp16 tables + exp + segment-sum.
//   16 lanes per edge; lane owns 4 dims -> one 8B load per gathered row
//   (one 128B line per warp-request per row). No max-subtraction: logits are
//   O(1), exp(x)/sum exp(x) == softmax.
// ---------------------------------------------------------------------------
__global__ void __launch_bounds__(256)
k_logits(const int*   __restrict__ edges,
         const float* __restrict__ ws,
         const float* __restrict__ bvec,
         const float* __restrict__ out_w,
         const float* __restrict__ out_b,
         int E)
{
    __shared__ float s_ws[8 * DIM];
    __shared__ float s_b[DIM], s_ow[DIM], s_ob[DIM];
    int tid = threadIdx.x;
    for (int i = tid; i < 8 * DIM; i += blockDim.x) s_ws[i] = ws[i];
    for (int i = tid; i < DIM; i += blockDim.x) {
        s_b[i]  = bvec[i];
        s_ow[i] = out_w[i];
        s_ob[i] = out_b[i];
    }
    __syncthreads();

    int gt   = blockIdx.x * blockDim.x + tid;
    int edge = gt >> 4;
    int lane = tid & 15;
    unsigned gmask = 0xFFFFu << (tid & 16);
    if (edge >= E) return;

    // edge row: two 16B broadcast loads
    const int4* rp = reinterpret_cast<const int4*>(edges + (size_t)edge * 8);
    int4 ra = __ldg(rp);       // idx, vi, vj, rel
    int4 rb = __ldg(rp + 1);   // idx_vi, idx_vj, e2vi, e2vj
    int vi = ra.y, vj = ra.z, rl = ra.w;
    int ivi = rb.x, e2vi = rb.z, e2vj = rb.w;

    int d0 = lane * 4;
    uint2 ua = *reinterpret_cast<const uint2*>(g_hc_h  + (size_t)e2vi * DIM + d0);
    uint2 uc = *reinterpret_cast<const uint2*>(g_hc_h  + (size_t)e2vj * DIM + d0);
    uint2 uA = *reinterpret_cast<const uint2*>(g_hu_h  + (size_t)vi   * DIM + d0);
    uint2 uC = *reinterpret_cast<const uint2*>(g_hu_h  + (size_t)vj   * DIM + d0);
    uint2 ur = *reinterpret_cast<const uint2*>(g_rel_h + (size_t)rl   * DIM + d0);

#define UNPACK4(u, f)                                                        \
    {   __half2 _l = *reinterpret_cast<__half2*>(&(u).x);                    \
        __half2 _h = *reinterpret_cast<__half2*>(&(u).y);                    \
        float2 _fl = __half22float2(_l), _fh = __half22float2(_h);           \
        f[0] = _fl.x; f[1] = _fl.y; f[2] = _fh.x; f[3] = _fh.y; }

    float av[4], cv[4], Av[4], Cv[4], rv[4];
    UNPACK4(ua, av) UNPACK4(uc, cv) UNPACK4(uA, Av) UNPACK4(uC, Cv) UNPACK4(ur, rv)
#undef UNPACK4

    float acc = 0.0f;
#pragma unroll
    for (int j = 0; j < 4; j++) {
        int d = d0 + j;
        float rr = rv[j];
        float f = s_b[d]
                + av[j] * cv[j] * fmaf(s_ws[1 * DIM + d], rr, s_ws[0 * DIM + d])
                + av[j] * Cv[j] * fmaf(s_ws[3 * DIM + d], rr, s_ws[2 * DIM + d])
                + Av[j] * cv[j] * fmaf(s_ws[5 * DIM + d], rr, s_ws[4 * DIM + d])
                + Av[j] * Cv[j] * fmaf(s_ws[7 * DIM + d], rr, s_ws[6 * DIM + d]);
        acc += fmaxf(f, 0.0f) * s_ow[d] + s_ob[d];
    }

#pragma unroll
    for (int off = 8; off; off >>= 1)
        acc += __shfl_xor_sync(gmask, acc, off);

    if (lane == 0) {
        float ev = __expf(acc);
        g_ev[edge] = ev;
        atomicAdd(&g_segsum[ivi], ev);
    }
}

// ---------------------------------------------------------------------------
// K2: thread-per-edge scatter + warp-aggregated rowsum.
// ---------------------------------------------------------------------------
__global__ void __launch_bounds__(256)
k_scatter(const int*   __restrict__ edges,
          const float* __restrict__ na,
          const float* __restrict__ ey,
          float*       __restrict__ out,
          int N, int E)
{
    int e  = blockIdx.x * blockDim.x + threadIdx.x;
    int ec = min(e, E - 1);
    const int4* rp = reinterpret_cast<const int4*>(edges + (size_t)ec * 8);
    int4 ra = __ldg(rp);
    int idx = ra.x;

    float ta = 0.0f;
    if (e < E) {
        int4 rb = __ldg(rp + 1);
        float tr = g_ev[e] * __fdividef(1.0f, g_segsum[rb.x]);
        ta = __ldg(na + (size_t)idx * N + ra.y) * tr * __ldg(ey + e);
        atomicAdd(&out[(size_t)idx * N + ra.z], ta);
    }

    int idx0 = __shfl_sync(0xffffffffu, idx, 0);
    bool uni = __all_sync(0xffffffffu, idx == idx0);
    if (uni) {
        float w = ta;
#pragma unroll
        for (int off = 16; off; off >>= 1)
            w += __shfl_xor_sync(0xffffffffu, w, off);
        if ((threadIdx.x & 31) == 0 && w != 0.0f)
            atomicAdd(&g_rowsum[idx0], w);
    } else if (ta != 0.0f) {
        atomicAdd(&g_rowsum[idx], ta);
    }
}

// ---------------------------------------------------------------------------
// K3: normalize rows (float4, reciprocal) + re-zero scratch for next call.
// ---------------------------------------------------------------------------
__global__ void k_norm(float4* __restrict__ out4, int N, int n4, int E) {
    int i = blockIdx.x * blockDim.x + threadIdx.x;
    int stride = gridDim.x * blockDim.x;
    if (i < n4) {
        int row = (i * 4) / N;
        float inv = __fdividef(1.0f, g_rowsum[row]);
        float4 v = out4[i];
        v.x *= inv; v.y *= inv; v.z *= inv; v.w *= inv;
        out4[i] = v;
    }
    float4* ss4 = reinterpret_cast<float4*>(g_segsum);
    int e4 = (E + 3) / 4;
    float4 z = make_float4(0.f, 0.f, 0.f, 0.f);
    for (int k = i; k < e4; k += stride) ss4[k] = z;
    if (i < 64) g_rowsum[i] = 0.0f;
}

// ---------------------------------------------------------------------------
// Inputs (metadata order):
//  0 node_attention (B*N f32)   1 selected_edges (E*8 i32)  2 edges_y (E f32)
//  3 hidden_con (n_vis*64 f32)  4 hidden_uncon (N*64 f32)   5 rel_emb (R*64 f32)
//  6 ws (8*64 f32)  7 b (64)  8 out_w (64)  9 out_b (64)
// ---------------------------------------------------------------------------
extern "C" void kernel_launch(void* const* d_in, const int* in_sizes, int n_in,
                              void* d_out, int out_size)
{
    const float* na   = (const float*)d_in[0];
    const int*   sel  = (const int*)  d_in[1];
    const float* ey   = (const float*)d_in[2];
    const float* hc   = (const float*)d_in[3];
    const float* hu   = (const float*)d_in[4];
    const float* rel  = (const float*)d_in[5];
    const float* ws   = (const float*)d_in[6];
    const float* bv   = (const float*)d_in[7];
    const float* ow   = (const float*)d_in[8];
    const float* ob   = (const float*)d_in[9];
    float* out = (float*)d_out;

    int E  = in_sizes[2];
    int BN = in_sizes[0];
    int N  = in_sizes[4] / DIM;
    int n4 = BN / 4;

    k_prep<<<1024, 256>>>((const float4*)hc, (const float4*)hu,
                          (const float4*)rel, (float4*)out,
                          n4, in_sizes[3] / 4, in_sizes[4] / 4, in_sizes[5] / 4);

    int blocks1 = (E * 16 + 255) / 256;
    k_logits<<<blocks1, 256>>>(sel, ws, bv, ow, ob, E);

    int tb = 256;
    k_scatter<<<(E + tb - 1) / tb, tb>>>(sel, na, ey, out, N, E);
    k_norm<<<(n4 + 255) / 256, 256>>>((float4*)out, N, n4, E);
}

// round 14
// speedup vs baseline: 2.3467x; 1.9172x over previous
#include <cuda_runtime.h>
#include <cuda_bf16.h>

#define E_MAX   250000
#define DIM     64

// Scratch (alloc-free rule: __device__ globals; zero-initialized at load).
// g_segsum / g_rowsum are re-zeroed at the END of each call (k_norm).
__device__ float g_ev[E_MAX];
__device__ float g_segsum[E_MAX];
__device__ float g_rowsum[64];

// ---------------------------------------------------------------------------
// K1: persistent grid-stride logits + exp + segsum (+ out-zero prologue).
//   16 lanes per edge; lane owns dims 4*lane..4*lane+3. Weight slice for those
//   4 dims lives in REGISTERS, loaded once per thread and reused across ~35
//   edges (no smem, no per-edge LDS). out_b dropped: it adds a constant to
//   every logit, which cancels in exp(x)/sum exp(x). No max-subtraction:
//   logits are O(1), fp32-exp safe.
// ---------------------------------------------------------------------------
__global__ void __launch_bounds__(256, 3)
k_logits(const int*   __restrict__ edges,
         const float* __restrict__ hc,
         const float* __restrict__ hu,
         const float* __restrict__ rel_emb,
         const float* __restrict__ ws,
         const float* __restrict__ bvec,
         const float* __restrict__ out_w,
         float4*      __restrict__ out4,
         int n4, int E, int ngroups)
{
    int tid = threadIdx.x;
    int gt  = blockIdx.x * blockDim.x + tid;
    int gstride = gridDim.x * blockDim.x;

    // zero the output tensor (k_logits never touches out otherwise)
    float4 z = make_float4(0.f, 0.f, 0.f, 0.f);
    for (int i = gt; i < n4; i += gstride) out4[i] = z;

    int lane = tid & 15;
    unsigned gmask = 0xFFFFu << (tid & 16);

    // per-thread weight slice (loop-invariant): dims 4*lane..4*lane+3
    const float4* ws4 = reinterpret_cast<const float4*>(ws);
    float wk[8][4];
#pragma unroll
    for (int k = 0; k < 8; k++) {
        float4 w = __ldg(ws4 + k * 16 + lane);
        wk[k][0] = w.x; wk[k][1] = w.y; wk[k][2] = w.z; wk[k][3] = w.w;
    }
    float4 b4 = __ldg(reinterpret_cast<const float4*>(bvec)  + lane);
    float4 o4 = __ldg(reinterpret_cast<const float4*>(out_w) + lane);
    float bv[4] = {b4.x, b4.y, b4.z, b4.w};
    float ov[4] = {o4.x, o4.y, o4.z, o4.w};

    int d0 = lane * 4;

    // persistent loop over edges
    for (int e = gt >> 4; e < E; e += ngroups) {
        const int4* rp = reinterpret_cast<const int4*>(edges + (size_t)e * 8);
        int4 ra = __ldg(rp);       // idx, vi, vj, rel
        int4 rb = __ldg(rp + 1);   // idx_vi, idx_vj, e2vi, e2vj

        float4 ga = __ldg(reinterpret_cast<const float4*>(hc      + (size_t)rb.z * DIM + d0));
        float4 gc = __ldg(reinterpret_cast<const float4*>(hc      + (size_t)rb.w * DIM + d0));
        float4 gA = __ldg(reinterpret_cast<const float4*>(hu      + (size_t)ra.y * DIM + d0));
        float4 gC = __ldg(reinterpret_cast<const float4*>(hu      + (size_t)ra.z * DIM + d0));
        float4 gr = __ldg(reinterpret_cast<const float4*>(rel_emb + (size_t)ra.w * DIM + d0));

        float av[4] = {ga.x, ga.y, ga.z, ga.w};
        float cv[4] = {gc.x, gc.y, gc.z, gc.w};
        float Av[4] = {gA.x, gA.y, gA.z, gA.w};
        float Cv[4] = {gC.x, gC.y, gC.z, gC.w};
        float rv[4] = {gr.x, gr.y, gr.z, gr.w};

        float acc = 0.0f;
#pragma unroll
        for (int j = 0; j < 4; j++) {
            float u01 = fmaf(wk[1][j], rv[j], wk[0][j]);
            float u23 = fmaf(wk[3][j], rv[j], wk[2][j]);
            float u45 = fmaf(wk[5][j], rv[j], wk[4][j]);
            float u67 = fmaf(wk[7][j], rv[j], wk[6][j]);
            float t1 = fmaf(Cv[j], u23, cv[j] * u01);
            float t2 = fmaf(Cv[j], u67, cv[j] * u45);
            float f  = fmaf(av[j], t1, fmaf(Av[j], t2, bv[j]));
            acc = fmaf(fmaxf(f, 0.0f), ov[j], acc);
        }

#pragma unroll
        for (int off = 8; off; off >>= 1)
            acc += __shfl_xor_sync(gmask, acc, off);

        if (lane == 0) {
            float ev = __expf(acc);
            g_ev[e] = ev;
            atomicAdd(&g_segsum[rb.x], ev);
        }
    }
}

// ---------------------------------------------------------------------------
// K2: thread-per-edge scatter + warp-aggregated rowsum.
// ---------------------------------------------------------------------------
__global__ void __launch_bounds__(256)
k_scatter(const int*   __restrict__ edges,
          const float* __restrict__ na,
          const float* __restrict__ ey,
          float*       __restrict__ out,
          int N, int E)
{
    int e  = blockIdx.x * blockDim.x + threadIdx.x;
    int ec = min(e, E - 1);
    const int4* rp = reinterpret_cast<const int4*>(edges + (size_t)ec * 8);
    int4 ra = __ldg(rp);
    int idx = ra.x;

    float ta = 0.0f;
    if (e < E) {
        int4 rb = __ldg(rp + 1);
        float tr = g_ev[e] * __fdividef(1.0f, g_segsum[rb.x]);
        ta = __ldg(na + (size_t)idx * N + ra.y) * tr * __ldg(ey + e);
        atomicAdd(&out[(size_t)idx * N + ra.z], ta);
    }

    int idx0 = __shfl_sync(0xffffffffu, idx, 0);
    bool uni = __all_sync(0xffffffffu, idx == idx0);
    if (uni) {
        float w = ta;
#pragma unroll
        for (int off = 16; off; off >>= 1)
            w += __shfl_xor_sync(0xffffffffu, w, off);
        if ((threadIdx.x & 31) == 0 && w != 0.0f)
            atomicAdd(&g_rowsum[idx0], w);
    } else if (ta != 0.0f) {
        atomicAdd(&g_rowsum[idx], ta);
    }
}

// ---------------------------------------------------------------------------
// K3: normalize rows (float4, reciprocal) + re-zero scratch for next call.
// ---------------------------------------------------------------------------
__global__ void k_norm(float4* __restrict__ out4, int N, int n4, int E) {
    int i = blockIdx.x * blockDim.x + threadIdx.x;
    int stride = gridDim.x * blockDim.x;
    if (i < n4) {
        int row = (i * 4) / N;
        float inv = __fdividef(1.0f, g_rowsum[row]);
        float4 v = out4[i];
        v.x *= inv; v.y *= inv; v.z *= inv; v.w *= inv;
        out4[i] = v;
    }
    float4* ss4 = reinterpret_cast<float4*>(g_segsum);
    int e4 = (E + 3) / 4;
    float4 z = make_float4(0.f, 0.f, 0.f, 0.f);
    for (int k = i; k < e4; k += stride) ss4[k] = z;
    if (i < 64) g_rowsum[i] = 0.0f;
}

// ---------------------------------------------------------------------------
// Inputs (metadata order):
//  0 node_attention (B*N f32)   1 selected_edges (E*8 i32)  2 edges_y (E f32)
//  3 hidden_con (n_vis*64 f32)  4 hidden_uncon (N*64 f32)   5 rel_emb (R*64 f32)
//  6 ws (8*64 f32)  7 b (64)  8 out_w (64)  9 out_b (64, unused — cancels)
// ---------------------------------------------------------------------------
extern "C" void kernel_launch(void* const* d_in, const int* in_sizes, int n_in,
                              void* d_out, int out_size)
{
    const float* na   = (const float*)d_in[0];
    const int*   sel  = (const int*)  d_in[1];
    const float* ey   = (const float*)d_in[2];
    const float* hc   = (const float*)d_in[3];
    const float* hu   = (const float*)d_in[4];
    const float* rel  = (const float*)d_in[5];
    const float* ws   = (const float*)d_in[6];
    const float* bv   = (const float*)d_in[7];
    const float* ow   = (const float*)d_in[8];
    float* out = (float*)d_out;

    int E  = in_sizes[2];
    int BN = in_sizes[0];
    int N  = in_sizes[4] / DIM;
    int n4 = BN / 4;

    // persistent: 3 blocks/SM x 148 SMs
    int blocks1  = 444;
    int ngroups  = blocks1 * 256 / 16;
    k_logits<<<blocks1, 256>>>(sel, hc, hu, rel, ws, bv, ow,
                               (float4*)out, n4, E, ngroups);

    int tb = 256;
    k_scatter<<<(E + tb - 1) / tb, tb>>>(sel, na, ey, out, N, E);
    k_norm<<<(n4 + 255) / 256, 256>>>((float4*)out, N, n4, E);
}